// round 12
// baseline (speedup 1.0000x reference)
#include <cuda_runtime.h>

// ---------------------------------------------------------------------------
// SLAYER SNN forward on GB300 (sm_103a), fp32, exact-order IIR.
// pool4 -> psp -> conv5x5(2->32) -> [psp+pool2+psp fused] -> conv3x3(32->64)
// -> [psp+pool2+psp fused] -> conv3x3(64->64) -> psp -> fc(4096->256, f-split)
// -> psp(sum partials) -> fc(256->11) -> psp.   N=4, T=300, stride TP=320.
// MAC kernels use fma.rn.f32x2 (2 fp32 MAC / issue slot), float4 loads.
// psppool: lane-owns-pooled-pixel, shuffle-free dual IIR.
// ---------------------------------------------------------------------------

#define T  300
#define TP 320
#define NB 4

#define A_SR 0.90483741803595957f   // exp(-1/10)
#define A_RF 0.36787944117144233f   // exp(-1)
#define C_SR 0.27182818284590452f   // e/10
#define C_RF -54.365636569180902f   // -2*10*e
#define THETA 10.0f

typedef unsigned long long u64;

// ---------------- scratch offsets (floats), stride TP ----------------
static const size_t OFF_P0  = 0;         // 4*2*32*32*320  = 2,621,440
static const size_t OFF_S0  = 2621440;   // 2,621,440
static const size_t OFF_A1  = 5242880;   // 4*32*32*32*320 = 41,943,040
static const size_t OFF_S2  = 47185920;  // 4*32*16*16*320 = 10,485,760
static const size_t OFF_A3  = 57671680;  // 4*64*16*16*320 = 20,971,520
static const size_t OFF_S4  = 78643200;  // 4*64*8*8*320   = 5,242,880
static const size_t OFF_A5  = 83886080;  // 5,242,880
static const size_t OFF_S5  = 89128960;  // 5,242,880
static const size_t OFF_A6P = 94371840;  // 4 partials * 4*256*320 = 1,310,720
static const size_t OFF_S6  = 95682560;  // 327,680
static const size_t OFF_A7  = 96010240;  // 4*11*320 = 14,080
// total 96,024,320 floats = 384.1 MB
__device__ float g_buf[96024320];

static const int PARTSZ = NB * 256 * TP;   // 327,680

// ---------------- f32x2 helpers ----------------
__device__ __forceinline__ u64 pack2(float a, float b) {
    u64 r; asm("mov.b64 %0, {%1, %2};" : "=l"(r) : "f"(a), "f"(b)); return r;
}
__device__ __forceinline__ void fma2(u64 &d, u64 a, u64 b) {
    asm("fma.rn.f32x2 %0, %1, %2, %0;" : "+l"(d) : "l"(a), "l"(b));
}

// ---------------- IIR step (exact op order, shared by all psp kernels) -----
__device__ __forceinline__ float iir_step(float &gp, float &hp, float &gr, float &hr,
                                          float xi)
{
    hp = __fmul_rn(A_SR, __fadd_rn(hp, gp));
    gp = __fadd_rn(__fmul_rn(A_SR, gp), xi);
    hr = __fmul_rn(A_RF, __fadd_rn(hr, gr));
    gr = __fmul_rn(A_RF, gr);
    float u = __fadd_rn(__fmul_rn(C_SR, hp), __fmul_rn(C_RF, hr));
    float s = (u >= THETA) ? 1.0f : 0.0f;
    gr = __fadd_rn(gr, s);
    return s;
}

// ---------------- sum pool (x 1.1*theta), float2 ----------------
template<int K>
__global__ __launch_bounds__(160) void pool_kernel(
    const float* __restrict__ src, float* __restrict__ dst,
    int C, int HO, int WO, int srcStride)
{
    int idx = blockIdx.x;
    int x = idx % WO; int r = idx / WO;
    int y = r % HO;   r /= HO;
    int c = r % C;    int n = r / C;
    const int WI = WO * K;
    const int HI = HO * K;
    const int t = threadIdx.x * 2;
    if (t >= T) return;
    const float* sp = src + (((((size_t)n * C + c) * HI + (size_t)y * K) * WI)
                             + (size_t)x * K) * srcStride + t;
    float sa = 0.f, sb = 0.f;
    #pragma unroll
    for (int i = 0; i < K; i++)
        #pragma unroll
        for (int j = 0; j < K; j++) {
            float2 v = *(const float2*)(sp + ((size_t)i * WI + j) * srcStride);
            sa += v.x; sb += v.y;
        }
    float2 o; o.x = 11.0f * sa; o.y = 11.0f * sb;
    *(float2*)(dst + (size_t)idx * TP + t) = o;
}

// ---------------- plain psp (+optional partial-sum input) ----------------
// Warp = 32 neurons; 32x64 (neuron x t) smem tiles, float2 coalesced IO.
template<int NPARTS>
__global__ __launch_bounds__(128) void psp_kernel(
    const float* __restrict__ src, float* __restrict__ dst,
    int nNeurons, int dstStride, int partStride)
{
    __shared__ float buf[4][32][65];
    const int warp = threadIdx.x >> 5, lane = threadIdx.x & 31;
    const int base = (blockIdx.x * 4 + warp) * 32;
    if (base >= nNeurons) return;

    float gp = 0.f, hp = 0.f, gr = 0.f, hr = 0.f;

    for (int tt = 0; tt < TP; tt += 64) {
        #pragma unroll
        for (int j = 0; j < 32; j++) {
            int ni = base + j;
            float2 v; v.x = 0.f; v.y = 0.f;
            if (ni < nNeurons && tt + 2 * lane < T) {
                const float* p = src + (size_t)ni * TP + tt + 2 * lane;
                v = *(const float2*)p;
                #pragma unroll
                for (int q = 1; q < NPARTS; q++) {
                    float2 w = *(const float2*)(p + (size_t)q * partStride);
                    v.x += w.x; v.y += w.y;
                }
            }
            buf[warp][j][2 * lane]     = v.x;
            buf[warp][j][2 * lane + 1] = v.y;
        }
        __syncwarp();
        #pragma unroll 4
        for (int k = 0; k < 64; k++) {
            float s = 0.f;
            if (tt + k < T)
                s = iir_step(gp, hp, gr, hr, buf[warp][lane][k]);
            buf[warp][lane][k] = s;
        }
        __syncwarp();
        #pragma unroll
        for (int j = 0; j < 32; j++) {
            int ni = base + j;
            if (ni < nNeurons && tt + 2 * lane < dstStride) {
                float2 v;
                v.x = buf[warp][j][2 * lane];
                v.y = buf[warp][j][2 * lane + 1];
                *(float2*)(dst + (size_t)ni * dstStride + tt + 2 * lane) = v;
            }
        }
        __syncwarp();
    }
}

// ---------------- fused psp -> pool2 -> psp (shuffle-free) ----------------
// Block = 128 pooled pixels; thread owns 1 pooled pixel and runs its 4
// source IIRs (ILP-4) + the pooled IIR. Source rows ordered q*128+p in a
// [src][t] smem tile (stride 33 -> conflict-free LDS). Pooled spikes
// overwrite the thread's own q=0 row before the transposed write-out.
__global__ __launch_bounds__(128) void psppool_kernel(
    const float* __restrict__ src, float* __restrict__ dst,
    int C, int HO, int WO)
{
    extern __shared__ float sm[];
    float* bufS  = sm;                       // [512][33]
    int*   srowT = (int*)(sm + 512 * 33);    // [512]

    const int tid = threadIdx.x;
    const int pbase = blockIdx.x * 128;
    const int HI = 2 * HO, WI = 2 * WO;

    // source-row table: row r = q*128 + p_local
    {
        int p = pbase + tid;
        int x = p % WO; int rr = p / WO;
        int y = rr % HO; rr /= HO;
        int c = rr % C;  int n = rr / C;
        #pragma unroll
        for (int q = 0; q < 4; q++)
            srowT[q * 128 + tid] =
                ((n * C + c) * HI + 2 * y + (q >> 1)) * WI + 2 * x + (q & 1);
    }
    __syncthreads();

    float gp[4], hp[4], gr[4], hr[4];
    #pragma unroll
    for (int q = 0; q < 4; q++) { gp[q] = 0.f; hp[q] = 0.f; gr[q] = 0.f; hr[q] = 0.f; }
    float gp2 = 0.f, hp2 = 0.f, gr2 = 0.f, hr2 = 0.f;

    const int rsub = tid >> 4;        // 0..7
    const int tcol = tid & 15;        // 0..15

    for (int tt = 0; tt < TP; tt += 32) {
        // load 512 rows x 32 t (coalesced along t)
        #pragma unroll 8
        for (int r0 = 0; r0 < 512; r0 += 8) {
            int r = r0 + rsub;
            int grow = srowT[r];
            float2 v = *(const float2*)(src + (size_t)grow * TP + tt + 2 * tcol);
            bufS[r * 33 + 2 * tcol]     = v.x;
            bufS[r * 33 + 2 * tcol + 1] = v.y;
        }
        __syncthreads();
        // dual IIR, 32 sequential steps
        #pragma unroll 4
        for (int k = 0; k < 32; k++) {
            float s2 = 0.f;
            if (tt + k < T) {
                float s[4];
                #pragma unroll
                for (int q = 0; q < 4; q++)
                    s[q] = iir_step(gp[q], hp[q], gr[q], hr[q],
                                    bufS[(q * 128 + tid) * 33 + k]);
                float sm01 = __fadd_rn(s[0], s[1]);
                float sm23 = __fadd_rn(s[2], s[3]);
                s2 = iir_step(gp2, hp2, gr2, hr2,
                              __fmul_rn(11.0f, __fadd_rn(sm01, sm23)));
            }
            bufS[tid * 33 + k] = s2;   // overwrite own q=0 row (already consumed)
        }
        __syncthreads();
        // write pooled spikes (coalesced along t)
        #pragma unroll 8
        for (int p0 = 0; p0 < 128; p0 += 8) {
            int p = p0 + rsub;
            float2 v;
            v.x = bufS[p * 33 + 2 * tcol];
            v.y = bufS[p * 33 + 2 * tcol + 1];
            *(float2*)(dst + (size_t)(pbase + p) * TP + tt + 2 * tcol) = v;
        }
        __syncthreads();
    }
}

// ---------------- per-timestep 2D conv, f32x2 packed, float4 loads ---------
// Block = 4 warps = 2 adjacent pixels x 2 ocg halves (input shared via L1).
// Lane covers t = 4*lane + 128*j (j=0,1, LDG.128) and t = 2*lane + 256 (u64).
template<int IC, int K, int PAD, int G>
__global__ __launch_bounds__(128) void conv_kernel(
    const float* __restrict__ src, float* __restrict__ dst,
    const float* __restrict__ w, int H, int W)
{
    constexpr int KK = K * K;
    constexpr int ICKK = IC * KK;
    __shared__ u64 swd[2 * G * ICKK];

    const int lane = threadIdx.x & 31;
    const int warp = threadIdx.x >> 5;
    const int n  = blockIdx.z;
    const int OC = gridDim.y * 2 * G;

    for (int i = threadIdx.x; i < 2 * G * ICKK; i += 128) {
        float v = w[(size_t)blockIdx.y * 2 * G * ICKK + i];
        swd[i] = pack2(v, v);
    }
    __syncthreads();

    const int pixel = blockIdx.x * 2 + (warp & 1);
    const int ocg   = blockIdx.y * 2 + (warp >> 1);
    const u64* wslice = swd + (size_t)(warp >> 1) * G * ICKK;
    const int x = pixel % W, y = pixel / W;

    u64 acc[5][G];
    #pragma unroll
    for (int j = 0; j < 5; j++)
        #pragma unroll
        for (int g = 0; g < G; g++) acc[j][g] = 0ull;

    const float* sb = src + ((size_t)n * IC * H * W) * TP;

    #pragma unroll
    for (int ky = 0; ky < K; ky++) {
        int iy = y + ky - PAD;
        if (iy < 0 || iy >= H) continue;
        #pragma unroll
        for (int kx = 0; kx < K; kx++) {
            int ix = x + kx - PAD;
            if (ix < 0 || ix >= W) continue;
            const float* tap = sb + (size_t)(iy * W + ix) * TP;
            #pragma unroll (IC <= 4 ? IC : 2)
            for (int ic = 0; ic < IC; ic++) {
                const float* p = tap + (size_t)ic * H * W * TP;
                ulonglong2 vA = *(const ulonglong2*)(p + 4 * lane);
                ulonglong2 vB = *(const ulonglong2*)(p + 128 + 4 * lane);
                u64 vC = *(const u64*)(p + 256 + 2 * lane);
                u64 v[5]; v[0] = vA.x; v[1] = vA.y; v[2] = vB.x; v[3] = vB.y; v[4] = vC;
                #pragma unroll
                for (int g = 0; g < G; g++) {
                    u64 wv = wslice[g * ICKK + ic * KK + ky * K + kx];
                    #pragma unroll
                    for (int j = 0; j < 5; j++)
                        fma2(acc[j][g], v[j], wv);
                }
            }
        }
    }

    float* dp = dst + ((size_t)(n * OC + ocg * G) * H * W + pixel) * TP;
    #pragma unroll
    for (int g = 0; g < G; g++) {
        float* base = dp + (size_t)g * H * W * TP;
        ulonglong2 oA; oA.x = acc[0][g]; oA.y = acc[1][g];
        ulonglong2 oB; oB.x = acc[2][g]; oB.y = acc[3][g];
        *(ulonglong2*)(base + 4 * lane) = oA;
        *(ulonglong2*)(base + 128 + 4 * lane) = oB;
        *(u64*)(base + 256 + 2 * lane) = acc[4][g];
    }
}

// ---------------- fully connected, f32x2 packed, optional f-split ----------
// grid (OC/G, N, FSPLITS); block 160 = 5 warps (t chunks of 64).
template<int G, int CF>
__global__ __launch_bounds__(160) void fc_kernel(
    const float* __restrict__ src, float* __restrict__ dst,
    const float* __restrict__ w, int INF, int OC, int fLen, int partStride)
{
    __shared__ u64 swd[G * CF];
    const int lane = threadIdx.x & 31, warp = threadIdx.x >> 5;
    const int og = blockIdx.x, n = blockIdx.y, fs = blockIdx.z;
    const int fbase = fs * fLen;
    const int tbase = warp * 64 + lane * 2;

    u64 acc[G];
    #pragma unroll
    for (int g = 0; g < G; g++) acc[g] = 0ull;

    for (int f0 = fbase; f0 < fbase + fLen; f0 += CF) {
        __syncthreads();
        for (int i = threadIdx.x; i < G * CF; i += 160) {
            float v = w[(size_t)(og * G + i / CF) * INF + f0 + (i % CF)];
            swd[i] = pack2(v, v);
        }
        __syncthreads();
        const float* sp = src + ((size_t)n * INF + f0) * TP + tbase;
        for (int f = 0; f < CF; f++) {
            u64 v = *(const u64*)(sp + (size_t)f * TP);
            #pragma unroll
            for (int g = 0; g < G; g++)
                fma2(acc[g], v, swd[g * CF + f]);
        }
    }

    float* dp = dst + (size_t)fs * partStride
                    + ((size_t)n * OC + og * G) * TP + tbase;
    #pragma unroll
    for (int g = 0; g < G; g++)
        *(u64*)(dp + (size_t)g * TP) = acc[g];
}

// ---------------------------------------------------------------------------
extern "C" void kernel_launch(void* const* d_in, const int* in_sizes, int n_in,
                              void* d_out, int out_size)
{
    const float* s_in = (const float*)d_in[0];   // (4,2,128,128,300)
    const float* w1   = (const float*)d_in[1];   // (32,2,5,5)
    const float* w2   = (const float*)d_in[2];   // (64,32,3,3)
    const float* w3   = (const float*)d_in[3];   // (64,64,3,3)
    const float* w4a  = (const float*)d_in[4];   // (256,4096)
    const float* w4b  = (const float*)d_in[5];   // (11,256)
    float* out = (float*)d_out;                  // (4,11,300)

    float* buf = nullptr;
    cudaGetSymbolAddress((void**)&buf, g_buf);

    const int PSPPOOL_SMEM = (512 * 33 + 512) * 4;   // 69,632 B
    cudaFuncSetAttribute(psppool_kernel,
                         cudaFuncAttributeMaxDynamicSharedMemorySize, PSPPOOL_SMEM);

    float* P0  = buf + OFF_P0;  float* S0 = buf + OFF_S0;
    float* A1  = buf + OFF_A1;  float* S2 = buf + OFF_S2;
    float* A3  = buf + OFF_A3;  float* S4 = buf + OFF_S4;
    float* A5  = buf + OFF_A5;  float* S5 = buf + OFF_S5;
    float* A6P = buf + OFF_A6P; float* S6 = buf + OFF_S6;
    float* A7  = buf + OFF_A7;

    // L0: pool4 (4,2,128,128)->(4,2,32,32), psp
    pool_kernel<4><<<NB * 2 * 32 * 32, 160>>>(s_in, P0, 2, 32, 32, T);
    psp_kernel<1><<<64, 128>>>(P0, S0, NB * 2 * 32 * 32, TP, 0);

    // L1: conv 5x5, 2->32, pad2 ; fused psp+pool2+psp -> S2 (4,32,16,16)
    conv_kernel<2, 5, 2, 8><<<dim3(512, 2, NB), 128>>>(S0, A1, w1, 32, 32);
    psppool_kernel<<<256, 128, PSPPOOL_SMEM>>>(A1, S2, 32, 16, 16);

    // L3: conv 3x3, 32->64, pad1 ; fused psp+pool2+psp -> S4 (4,64,8,8)
    conv_kernel<32, 3, 1, 8><<<dim3(128, 4, NB), 128>>>(S2, A3, w2, 16, 16);
    psppool_kernel<<<128, 128, PSPPOOL_SMEM>>>(A3, S4, 64, 8, 8);

    // L5: conv 3x3, 64->64, pad1 ; psp (full 16384 neurons)
    conv_kernel<64, 3, 1, 8><<<dim3(32, 4, NB), 128>>>(S4, A5, w3, 8, 8);
    psp_kernel<1><<<128, 128>>>(A5, S5, NB * 64 * 8 * 8, TP, 0);

    // L6: fc 4096->256 split over f into 4 partials; psp sums partials
    fc_kernel<8, 512><<<dim3(32, NB, 4), 160>>>(S5, A6P, w4a, 4096, 256, 1024, PARTSZ);
    psp_kernel<4><<<8, 128>>>(A6P, S6, NB * 256, TP, PARTSZ);

    // L7: fc 256->11 ; psp -> out (stride 300)
    fc_kernel<11, 256><<<dim3(1, NB, 1), 160>>>(S6, A7, w4b, 256, 11, 256, 0);
    psp_kernel<1><<<1, 128>>>(A7, out, NB * 11, T, 0);
}

// round 14
// speedup vs baseline: 1.4997x; 1.4997x over previous
#include <cuda_runtime.h>

// ---------------------------------------------------------------------------
// SLAYER SNN forward on GB300 (sm_103a), fp32, exact-order IIR.
// pool4 -> psp -> conv5x5(2->32) -> [psp+pool2+psp fused] -> conv3x3(32->64)
// -> [psp+pool2+psp fused] -> conv3x3(64->64) -> psp -> fc(4096->256, f-split)
// -> psp(sum partials) -> fc(256->11) -> psp.   N=4, T=300, stride TP=320.
// MAC kernels: fma.rn.f32x2 (2 fp32 MAC / slot) + float4 loads.
// psppool: warp-per-8-pooled-pixels, butterfly-shuffle pooling (R6 design —
// the R11 "shuffle-free" block-serial variant starved latency hiding: 6% issue).
// ---------------------------------------------------------------------------

#define T  300
#define TP 320
#define NB 4

#define A_SR 0.90483741803595957f   // exp(-1/10)
#define A_RF 0.36787944117144233f   // exp(-1)
#define C_SR 0.27182818284590452f   // e/10
#define C_RF -54.365636569180902f   // -2*10*e
#define THETA 10.0f

typedef unsigned long long u64;

// ---------------- scratch offsets (floats), stride TP ----------------
static const size_t OFF_P0  = 0;         // 4*2*32*32*320  = 2,621,440
static const size_t OFF_S0  = 2621440;   // 2,621,440
static const size_t OFF_A1  = 5242880;   // 4*32*32*32*320 = 41,943,040
static const size_t OFF_S2  = 47185920;  // 4*32*16*16*320 = 10,485,760
static const size_t OFF_A3  = 57671680;  // 4*64*16*16*320 = 20,971,520
static const size_t OFF_S4  = 78643200;  // 4*64*8*8*320   = 5,242,880
static const size_t OFF_A5  = 83886080;  // 5,242,880
static const size_t OFF_S5  = 89128960;  // 5,242,880
static const size_t OFF_A6P = 94371840;  // 4 partials * 4*256*320 = 1,310,720
static const size_t OFF_S6  = 95682560;  // 327,680
static const size_t OFF_A7  = 96010240;  // 4*11*320 = 14,080
// total 96,024,320 floats = 384.1 MB
__device__ float g_buf[96024320];

static const int PARTSZ = NB * 256 * TP;   // 327,680

// ---------------- f32x2 helpers ----------------
__device__ __forceinline__ u64 pack2(float a, float b) {
    u64 r; asm("mov.b64 %0, {%1, %2};" : "=l"(r) : "f"(a), "f"(b)); return r;
}
__device__ __forceinline__ void fma2(u64 &d, u64 a, u64 b) {
    asm("fma.rn.f32x2 %0, %1, %2, %0;" : "+l"(d) : "l"(a), "l"(b));
}

// ---------------- IIR step (exact op order, shared by all psp kernels) -----
__device__ __forceinline__ float iir_step(float &gp, float &hp, float &gr, float &hr,
                                          float xi)
{
    hp = __fmul_rn(A_SR, __fadd_rn(hp, gp));
    gp = __fadd_rn(__fmul_rn(A_SR, gp), xi);
    hr = __fmul_rn(A_RF, __fadd_rn(hr, gr));
    gr = __fmul_rn(A_RF, gr);
    float u = __fadd_rn(__fmul_rn(C_SR, hp), __fmul_rn(C_RF, hr));
    float s = (u >= THETA) ? 1.0f : 0.0f;
    gr = __fadd_rn(gr, s);
    return s;
}

// ---------------- sum pool (x 1.1*theta), float2 ----------------
template<int K>
__global__ __launch_bounds__(160) void pool_kernel(
    const float* __restrict__ src, float* __restrict__ dst,
    int C, int HO, int WO, int srcStride)
{
    int idx = blockIdx.x;
    int x = idx % WO; int r = idx / WO;
    int y = r % HO;   r /= HO;
    int c = r % C;    int n = r / C;
    const int WI = WO * K;
    const int HI = HO * K;
    const int t = threadIdx.x * 2;
    if (t >= T) return;
    const float* sp = src + (((((size_t)n * C + c) * HI + (size_t)y * K) * WI)
                             + (size_t)x * K) * srcStride + t;
    float sa = 0.f, sb = 0.f;
    #pragma unroll
    for (int i = 0; i < K; i++)
        #pragma unroll
        for (int j = 0; j < K; j++) {
            float2 v = *(const float2*)(sp + ((size_t)i * WI + j) * srcStride);
            sa += v.x; sb += v.y;
        }
    float2 o; o.x = 11.0f * sa; o.y = 11.0f * sb;
    *(float2*)(dst + (size_t)idx * TP + t) = o;
}

// ---------------- plain psp (+optional partial-sum input) ----------------
// Warp = 32 neurons; 32x64 (neuron x t) smem tiles, float2 coalesced IO.
template<int NPARTS>
__global__ __launch_bounds__(128) void psp_kernel(
    const float* __restrict__ src, float* __restrict__ dst,
    int nNeurons, int dstStride, int partStride)
{
    __shared__ float buf[4][32][65];
    const int warp = threadIdx.x >> 5, lane = threadIdx.x & 31;
    const int base = (blockIdx.x * 4 + warp) * 32;
    if (base >= nNeurons) return;

    float gp = 0.f, hp = 0.f, gr = 0.f, hr = 0.f;

    for (int tt = 0; tt < TP; tt += 64) {
        #pragma unroll
        for (int j = 0; j < 32; j++) {
            int ni = base + j;
            float2 v; v.x = 0.f; v.y = 0.f;
            if (ni < nNeurons && tt + 2 * lane < T) {
                const float* p = src + (size_t)ni * TP + tt + 2 * lane;
                v = *(const float2*)p;
                #pragma unroll
                for (int q = 1; q < NPARTS; q++) {
                    float2 w = *(const float2*)(p + (size_t)q * partStride);
                    v.x += w.x; v.y += w.y;
                }
            }
            buf[warp][j][2 * lane]     = v.x;
            buf[warp][j][2 * lane + 1] = v.y;
        }
        __syncwarp();
        #pragma unroll 4
        for (int k = 0; k < 64; k++) {
            float s = 0.f;
            if (tt + k < T)
                s = iir_step(gp, hp, gr, hr, buf[warp][lane][k]);
            buf[warp][lane][k] = s;
        }
        __syncwarp();
        #pragma unroll
        for (int j = 0; j < 32; j++) {
            int ni = base + j;
            if (ni < nNeurons && tt + 2 * lane < dstStride) {
                float2 v;
                v.x = buf[warp][j][2 * lane];
                v.y = buf[warp][j][2 * lane + 1];
                *(float2*)(dst + (size_t)ni * dstStride + tt + 2 * lane) = v;
            }
        }
        __syncwarp();
    }
}

// ---------------- fused psp -> pool2 -> psp (warp + shuffle, R6) ----------
// Warp = 8 pooled pixels x 4 (2x2) sources = 32 source neurons.
// IIR1 on sources (lane = source), spikes pooled via 2 butterfly shuffles,
// IIR2 on pooled neurons inline. Writes pooled spikes only.
__global__ __launch_bounds__(128) void psppool_kernel(
    const float* __restrict__ src, float* __restrict__ dst,
    int C, int HO, int WO)
{
    __shared__ float bufS[4][32][65];
    __shared__ float bufP[4][8][65];
    const int warp = threadIdx.x >> 5, lane = threadIdx.x & 31;
    const int pb = (blockIdx.x * 4 + warp) * 8;     // pooled base of this warp

    // lane's own source row (source grid is 2H x 2W), shuffled to peers in load
    int pi = pb + (lane >> 2);
    int x = pi % WO; int rr = pi / WO;
    int y = rr % HO; rr /= HO;
    int c = rr % C;  int n = rr / C;
    const int HI = 2 * HO, WI = 2 * WO;
    int srow = ((n * C + c) * HI + 2 * y + ((lane >> 1) & 1)) * WI
               + 2 * x + (lane & 1);

    float gp = 0.f, hp = 0.f, gr = 0.f, hr = 0.f;       // source IIR
    float gp2 = 0.f, hp2 = 0.f, gr2 = 0.f, hr2 = 0.f;   // pooled IIR

    for (int tt = 0; tt < TP; tt += 64) {
        #pragma unroll
        for (int j = 0; j < 32; j++) {
            int r = __shfl_sync(0xffffffffu, srow, j);
            float2 v = *(const float2*)(src + (size_t)r * TP + tt + 2 * lane);
            bufS[warp][j][2 * lane]     = v.x;
            bufS[warp][j][2 * lane + 1] = v.y;
        }
        __syncwarp();
        #pragma unroll 4
        for (int k = 0; k < 64; k++) {
            float s2 = 0.f;
            if (tt + k < T) {
                float s = iir_step(gp, hp, gr, hr, bufS[warp][lane][k]);
                float sm = s + __shfl_xor_sync(0xffffffffu, s, 1);
                sm = sm + __shfl_xor_sync(0xffffffffu, sm, 2);
                s2 = iir_step(gp2, hp2, gr2, hr2, __fmul_rn(11.0f, sm));
            }
            if ((lane & 3) == 0) bufP[warp][lane >> 2][k] = s2;
        }
        __syncwarp();
        #pragma unroll
        for (int j2 = 0; j2 < 8; j2++) {
            float2 v;
            v.x = bufP[warp][j2][2 * lane];
            v.y = bufP[warp][j2][2 * lane + 1];
            *(float2*)(dst + (size_t)(pb + j2) * TP + tt + 2 * lane) = v;
        }
        __syncwarp();
    }
}

// ---------------- per-timestep 2D conv, f32x2 packed, float4 loads ---------
// Block = 4 warps = 2 adjacent pixels x 2 ocg halves (input shared via L1).
// Lane covers t = 4*lane + 128*j (j=0,1, LDG.128) and t = 2*lane + 256 (u64).
template<int IC, int K, int PAD, int G>
__global__ __launch_bounds__(128) void conv_kernel(
    const float* __restrict__ src, float* __restrict__ dst,
    const float* __restrict__ w, int H, int W)
{
    constexpr int KK = K * K;
    constexpr int ICKK = IC * KK;
    __shared__ u64 swd[2 * G * ICKK];

    const int lane = threadIdx.x & 31;
    const int warp = threadIdx.x >> 5;
    const int n  = blockIdx.z;
    const int OC = gridDim.y * 2 * G;

    for (int i = threadIdx.x; i < 2 * G * ICKK; i += 128) {
        float v = w[(size_t)blockIdx.y * 2 * G * ICKK + i];
        swd[i] = pack2(v, v);
    }
    __syncthreads();

    const int pixel = blockIdx.x * 2 + (warp & 1);
    const int ocg   = blockIdx.y * 2 + (warp >> 1);
    const u64* wslice = swd + (size_t)(warp >> 1) * G * ICKK;
    const int x = pixel % W, y = pixel / W;

    u64 acc[5][G];
    #pragma unroll
    for (int j = 0; j < 5; j++)
        #pragma unroll
        for (int g = 0; g < G; g++) acc[j][g] = 0ull;

    const float* sb = src + ((size_t)n * IC * H * W) * TP;

    #pragma unroll
    for (int ky = 0; ky < K; ky++) {
        int iy = y + ky - PAD;
        if (iy < 0 || iy >= H) continue;
        #pragma unroll
        for (int kx = 0; kx < K; kx++) {
            int ix = x + kx - PAD;
            if (ix < 0 || ix >= W) continue;
            const float* tap = sb + (size_t)(iy * W + ix) * TP;
            #pragma unroll (IC <= 4 ? IC : 2)
            for (int ic = 0; ic < IC; ic++) {
                const float* p = tap + (size_t)ic * H * W * TP;
                ulonglong2 vA = *(const ulonglong2*)(p + 4 * lane);
                ulonglong2 vB = *(const ulonglong2*)(p + 128 + 4 * lane);
                u64 vC = *(const u64*)(p + 256 + 2 * lane);
                u64 v[5]; v[0] = vA.x; v[1] = vA.y; v[2] = vB.x; v[3] = vB.y; v[4] = vC;
                #pragma unroll
                for (int g = 0; g < G; g++) {
                    u64 wv = wslice[g * ICKK + ic * KK + ky * K + kx];
                    #pragma unroll
                    for (int j = 0; j < 5; j++)
                        fma2(acc[j][g], v[j], wv);
                }
            }
        }
    }

    float* dp = dst + ((size_t)(n * OC + ocg * G) * H * W + pixel) * TP;
    #pragma unroll
    for (int g = 0; g < G; g++) {
        float* base = dp + (size_t)g * H * W * TP;
        ulonglong2 oA; oA.x = acc[0][g]; oA.y = acc[1][g];
        ulonglong2 oB; oB.x = acc[2][g]; oB.y = acc[3][g];
        *(ulonglong2*)(base + 4 * lane) = oA;
        *(ulonglong2*)(base + 128 + 4 * lane) = oB;
        *(u64*)(base + 256 + 2 * lane) = acc[4][g];
    }
}

// ---------------- fully connected, f32x2 packed, optional f-split ----------
// grid (OC/G, N, FSPLITS); block 160 = 5 warps (t chunks of 64).
template<int G, int CF>
__global__ __launch_bounds__(160) void fc_kernel(
    const float* __restrict__ src, float* __restrict__ dst,
    const float* __restrict__ w, int INF, int OC, int fLen, int partStride)
{
    __shared__ u64 swd[G * CF];
    const int lane = threadIdx.x & 31, warp = threadIdx.x >> 5;
    const int og = blockIdx.x, n = blockIdx.y, fs = blockIdx.z;
    const int fbase = fs * fLen;
    const int tbase = warp * 64 + lane * 2;

    u64 acc[G];
    #pragma unroll
    for (int g = 0; g < G; g++) acc[g] = 0ull;

    for (int f0 = fbase; f0 < fbase + fLen; f0 += CF) {
        __syncthreads();
        for (int i = threadIdx.x; i < G * CF; i += 160) {
            float v = w[(size_t)(og * G + i / CF) * INF + f0 + (i % CF)];
            swd[i] = pack2(v, v);
        }
        __syncthreads();
        const float* sp = src + ((size_t)n * INF + f0) * TP + tbase;
        for (int f = 0; f < CF; f++) {
            u64 v = *(const u64*)(sp + (size_t)f * TP);
            #pragma unroll
            for (int g = 0; g < G; g++)
                fma2(acc[g], v, swd[g * CF + f]);
        }
    }

    float* dp = dst + (size_t)fs * partStride
                    + ((size_t)n * OC + og * G) * TP + tbase;
    #pragma unroll
    for (int g = 0; g < G; g++)
        *(u64*)(dp + (size_t)g * TP) = acc[g];
}

// ---------------------------------------------------------------------------
extern "C" void kernel_launch(void* const* d_in, const int* in_sizes, int n_in,
                              void* d_out, int out_size)
{
    const float* s_in = (const float*)d_in[0];   // (4,2,128,128,300)
    const float* w1   = (const float*)d_in[1];   // (32,2,5,5)
    const float* w2   = (const float*)d_in[2];   // (64,32,3,3)
    const float* w3   = (const float*)d_in[3];   // (64,64,3,3)
    const float* w4a  = (const float*)d_in[4];   // (256,4096)
    const float* w4b  = (const float*)d_in[5];   // (11,256)
    float* out = (float*)d_out;                  // (4,11,300)

    float* buf = nullptr;
    cudaGetSymbolAddress((void**)&buf, g_buf);

    float* P0  = buf + OFF_P0;  float* S0 = buf + OFF_S0;
    float* A1  = buf + OFF_A1;  float* S2 = buf + OFF_S2;
    float* A3  = buf + OFF_A3;  float* S4 = buf + OFF_S4;
    float* A5  = buf + OFF_A5;  float* S5 = buf + OFF_S5;
    float* A6P = buf + OFF_A6P; float* S6 = buf + OFF_S6;
    float* A7  = buf + OFF_A7;

    // L0: pool4 (4,2,128,128)->(4,2,32,32), psp
    pool_kernel<4><<<NB * 2 * 32 * 32, 160>>>(s_in, P0, 2, 32, 32, T);
    psp_kernel<1><<<64, 128>>>(P0, S0, NB * 2 * 32 * 32, TP, 0);

    // L1: conv 5x5, 2->32, pad2 ; fused psp+pool2+psp -> S2 (4,32,16,16)
    conv_kernel<2, 5, 2, 8><<<dim3(512, 2, NB), 128>>>(S0, A1, w1, 32, 32);
    psppool_kernel<<<1024, 128>>>(A1, S2, 32, 16, 16);

    // L3: conv 3x3, 32->64, pad1 ; fused psp+pool2+psp -> S4 (4,64,8,8)
    conv_kernel<32, 3, 1, 8><<<dim3(128, 4, NB), 128>>>(S2, A3, w2, 16, 16);
    psppool_kernel<<<512, 128>>>(A3, S4, 64, 8, 8);

    // L5: conv 3x3, 64->64, pad1 ; psp (full 16384 neurons)
    conv_kernel<64, 3, 1, 8><<<dim3(32, 4, NB), 128>>>(S4, A5, w3, 8, 8);
    psp_kernel<1><<<128, 128>>>(A5, S5, NB * 64 * 8 * 8, TP, 0);

    // L6: fc 4096->256 split over f into 4 partials; psp sums partials
    fc_kernel<8, 512><<<dim3(32, NB, 4), 160>>>(S5, A6P, w4a, 4096, 256, 1024, PARTSZ);
    psp_kernel<4><<<8, 128>>>(A6P, S6, NB * 256, TP, PARTSZ);

    // L7: fc 256->11 ; psp -> out (stride 300)
    fc_kernel<11, 256><<<dim3(1, NB, 1), 160>>>(S6, A7, w4b, 256, 11, 256, 0);
    psp_kernel<1><<<1, 128>>>(A7, out, NB * 11, T, 0);
}